// round 17
// baseline (speedup 1.0000x reference)
#include <cuda_runtime.h>
#include <cstdint>

#define N_NODES    100000
#define EMB_DIM    128
#define BATCH      16384
#define NUM_SAMPLE 25

#define VEC_PER_ROW (EMB_DIM / 4)   // 32 float4 per row

// FINAL kernel. Best measured 16.64 us; reproducible band 16.6-17.1 us
// (board clock noise). At the measured B300 LTS sector ceiling:
// 16384x25 gathers x 16 sectors / 184 slices ~= 17.8 us profiled wall.
//
// Design: one CTA == one warp == one row. Lane l<25 holds sample l's index;
// the 25-deep unrolled loop broadcasts indices via SHFL and issues
// LDG.E.128 (512 B fully-coalesced per row-sample). ptxas at 64 regs keeps
// a deep gather stream in flight; 16384 concurrent warps saturate L2.
//
// Closed branches (all bench-falsified): fp16 shadow table x3 (20.5/21.0/21.2
// — convert pass + issue-bound gather), persistent grid (18.9 — static
// imbalance), 2-row/warp (19.2 — halved concurrency), cache hints
// __ldcg/__stcs (17.1 — lost L1 hits), grain sweep 256/128/64 (noise),
// node-major inversion (atomic RMW >= bytes saved, not run).
#define BLOCK_THREADS 32
#define GRID_BLOCKS   BATCH   // 16384

__global__ __launch_bounds__(BLOCK_THREADS) void mean_agg_kernel(
    const float4* __restrict__ emb,      // [N_NODES, 32] as float4
    const int* __restrict__ neigh,       // [BATCH, NUM_SAMPLE], int32
    float4* __restrict__ out)            // [BATCH, 32] as float4
{
    const int row  = blockIdx.x;
    const int lane = threadIdx.x;        // 0..31

    const int* nb = neigh + row * NUM_SAMPLE;
    int my_idx = (lane < NUM_SAMPLE) ? nb[lane] : 0;

    float4 acc = make_float4(0.f, 0.f, 0.f, 0.f);

    #pragma unroll
    for (int s = 0; s < NUM_SAMPLE; ++s) {
        int id = __shfl_sync(0xffffffffu, my_idx, s);
        float4 v = __ldg(&emb[(unsigned)id * VEC_PER_ROW + lane]);
        acc.x += v.x;
        acc.y += v.y;
        acc.z += v.z;
        acc.w += v.w;
    }

    const float inv = 1.0f / (float)NUM_SAMPLE;   // 0.04
    acc.x *= inv; acc.y *= inv; acc.z *= inv; acc.w *= inv;

    out[(unsigned)row * VEC_PER_ROW + lane] = acc;
}

extern "C" void kernel_launch(void* const* d_in, const int* in_sizes, int n_in,
                              void* d_out, int out_size)
{
    const float4* emb   = (const float4*)d_in[0];
    const int*    neigh = (const int*)d_in[1];
    float4*       out   = (float4*)d_out;

    mean_agg_kernel<<<GRID_BLOCKS, BLOCK_THREADS>>>(emb, neigh, out);
}